// round 10
// baseline (speedup 1.0000x reference)
#include <cuda_runtime.h>
#include <cuda_fp16.h>
#include <cstdint>

// ---------------------------------------------------------------------------
// XORConv2d: out = conv_valid(x, 1-2W), x (32,128,64,64) f32, W (256,128,3,3)
// Implicit GEMM on mma.sync fp16/fp32. sm_103 plain target (no tcgen05).
// R10: CTA = 256co x 62px (ONE output row) -> warp tile 64x16, acc 32 regs,
// fragment double-buffer fits in registers (no ptxas demotion). Patch = 3
// input rows (48KB). grid (62,32)=1984 CTAs. Prep merged as R9.
// ---------------------------------------------------------------------------

#define BDIM   32
#define CIN    128
#define HH     64
#define WWID   64
#define COUT   256
#define HOUT   62
#define WOUT   62
#define PIX_PER_IMG (HOUT*WOUT)         // 3844

__device__ __half g_x[(size_t)BDIM * HH * WWID * CIN];   // NHWC fp16, 32 MB
__device__ __half g_w[9 * COUT * CIN];                   // (1-2W), [kp][co][cin]

static __device__ __forceinline__ uint32_t smem_u32(const void* p) {
    uint32_t a;
    asm("{ .reg .u64 t; cvta.to.shared.u64 t, %1; cvt.u32.u64 %0, t; }"
        : "=r"(a) : "l"(p));
    return a;
}

// ---------------------------------------------------------------------------
// Merged prep: blocks [0,8192) x NCHW f32 -> NHWC f16; rest build g_w = 1-2W.
// ---------------------------------------------------------------------------
#define XBLOCKS 8192
#define WBLOCKS ((COUT*CIN*9 + 255) / 256)    // 1152

__global__ void prep_all(const float* __restrict__ x,
                         const float* __restrict__ W) {
    if (blockIdx.x < XBLOCKS) {
        __shared__ float t[64][33];
        int bid = blockIdx.x;
        int bh  = bid & 2047;              // b*64 + h
        int rest = bid >> 11;              // 0..3
        int b  = bh >> 6, h = bh & 63;
        int c0 = (rest & 1) * 64;
        int w0 = (rest >> 1) * 32;
        int l  = threadIdx.x & 31, wy = threadIdx.x >> 5;   // 8 warps

        const float* src = x + ((size_t)(b * CIN + c0)) * (HH * WWID)
                             + h * WWID + w0;
#pragma unroll
        for (int i = 0; i < 8; i++)
            t[wy + 8 * i][l] = src[(size_t)(wy + 8 * i) * (HH * WWID) + l];
        __syncthreads();

#pragma unroll
        for (int i = 0; i < 4; i++) {
            int ww = wy + 8 * i;
            __half2 v = __floats2half2_rn(t[2 * l][ww], t[2 * l + 1][ww]);
            __half* drow = g_x + ((size_t)(bh * WWID) + w0 + ww) * CIN + c0;
            ((uint32_t*)drow)[l] = *(uint32_t*)&v;
        }
    } else {
        int idx = (blockIdx.x - XBLOCKS) * 256 + threadIdx.x;
        if (idx < COUT * CIN * 9) {
            int co  = idx / (CIN * 9);
            int r   = idx - co * (CIN * 9);
            int cin = r / 9;
            int kp  = r - cin * 9;
            g_w[(kp * COUT + co) * CIN + cin] =
                __float2half_rn(1.0f - 2.0f * W[idx]);
        }
    }
}

// ---------------------------------------------------------------------------
// Main: CTA = 256 co x 62 px (image b, output row r0).
// Patch = input rows r0..r0+2 (192 spatial x 256B = 48KB), loaded once.
// A double-buffered over 9 kp; register frag double-buffer (fits now).
// 16 warps: 4(M) x 4(N), warp tile 64co x 16px. grid (62, 32), 512 threads.
// ---------------------------------------------------------------------------
#define ASTAGE 65536
#define PATCH_ROWS 192
#define SMEM_BYTES (2*ASTAGE + PATCH_ROWS*256)   // 180224

__global__ void __launch_bounds__(512, 1)
xorconv_main(float* __restrict__ out) {
    extern __shared__ char smem[];
    const uint32_t sb = smem_u32(smem);
    const uint32_t PB = sb + 2 * ASTAGE;        // patch base

    const int tid = threadIdx.x;
    const int l   = tid & 31;
    const int w   = tid >> 5;          // 0..15
    const int wm  = w & 3;             // M group (64 co)
    const int wn  = w >> 2;            // N group (16 px)
    const int b   = blockIdx.y;
    const int r0  = blockIdx.x;        // output row (0..61)

    const int c    = tid & 15;         // 16B chunk in a 256B row
    const int rgrp = tid >> 4;         // 32 groups

    // Patch: 192 contiguous g_x rows starting at (b, r0, 0)
    {
        const __half* xsrc = g_x + ((size_t)(b * (HH * WWID) + r0 * WWID)) * CIN;
#pragma unroll
        for (int i = 0; i < 6; i++) {
            int r = rgrp + 32 * i;
            uint32_t sw = (uint32_t)r * 256u + (uint32_t)((c ^ (r & 7)) * 16);
            asm volatile("cp.async.cg.shared.global [%0], [%1], 16;"
                         :: "r"(PB + sw), "l"(xsrc + (size_t)r * CIN + c * 8));
        }
    }

    auto load_A = [&](int s, int kp) {
        uint32_t dA = sb + s * ASTAGE;
        const __half* wp = g_w + kp * COUT * CIN;
#pragma unroll
        for (int i = 0; i < 8; i++) {
            int r = rgrp + 32 * i;
            uint32_t sw = (uint32_t)r * 256u + (uint32_t)((c ^ (r & 7)) * 16);
            asm volatile("cp.async.cg.shared.global [%0], [%1], 16;"
                         :: "r"(dA + sw), "l"(wp + r * CIN + c * 8));
        }
        asm volatile("cp.async.commit_group;" ::: "memory");
    };

    load_A(0, 0);   // one group: patch + A0

    const uint32_t selA = (uint32_t)(l >> 4);
    const uint32_t selB = (uint32_t)((l >> 3) & 1);
    const int rowA0 = wm * 64 + (l & 15);
    int pr0;
    {
        int n = wn * 16 + (l & 7) + ((l >> 4) << 3);
        if (n > 61) n = 61;            // clamp pad lanes (never stored)
        pr0 = n;                       // spatial = wo within patch row 0
    }

    float acc[4][2][4];
#pragma unroll
    for (int a = 0; a < 4; a++)
#pragma unroll
        for (int bb = 0; bb < 2; bb++)
#pragma unroll
            for (int e = 0; e < 4; e++) acc[a][bb][e] = 0.f;

    uint32_t afr[2][4][4], bfr[2][4];

    for (int kp = 0; kp < 9; kp++) {
        asm volatile("cp.async.wait_group 0;" ::: "memory");
        __syncthreads();

        const uint32_t A = sb + (kp & 1) * ASTAGE;
        const int kh = kp / 3, kw = kp - 3 * kh;
        const uint32_t prow  = (uint32_t)(pr0 + kh * WWID + kw);
        const uint32_t pbase = PB + prow * 256u;

        auto load_frags = [&](int j, int p) {
#pragma unroll
            for (int fm = 0; fm < 4; fm++) {
                int r = rowA0 + fm * 16;
                uint32_t ch = ((uint32_t)(2 * j) + selA) ^ (uint32_t)(r & 7);
                uint32_t ad = A + (uint32_t)r * 256u + ch * 16u;
                asm volatile(
                    "ldmatrix.sync.aligned.m8n8.x4.shared.b16 {%0,%1,%2,%3}, [%4];"
                    : "=r"(afr[p][fm][0]), "=r"(afr[p][fm][1]),
                      "=r"(afr[p][fm][2]), "=r"(afr[p][fm][3])
                    : "r"(ad));
            }
            {
                uint32_t ch = ((uint32_t)(2 * j) + selB) ^ (prow & 7u);
                uint32_t ad = pbase + ch * 16u;
                asm volatile(
                    "ldmatrix.sync.aligned.m8n8.x4.shared.b16 {%0,%1,%2,%3}, [%4];"
                    : "=r"(bfr[p][0]), "=r"(bfr[p][1]),
                      "=r"(bfr[p][2]), "=r"(bfr[p][3])
                    : "r"(ad));
            }
        };

        load_frags(0, 0);
        if (kp < 8) load_A((kp + 1) & 1, kp + 1);   // overlaps compute below

#pragma unroll
        for (int j = 0; j < 8; j++) {            // K=128 in 8 x k16
            const int p = j & 1;
            if (j < 7) load_frags(j + 1, p ^ 1);
#pragma unroll
            for (int fm = 0; fm < 4; fm++)
#pragma unroll
                for (int nf = 0; nf < 2; nf++) {
                    asm volatile(
                        "mma.sync.aligned.m16n8k16.row.col.f32.f16.f16.f32 "
                        "{%0,%1,%2,%3}, {%4,%5,%6,%7}, {%8,%9}, {%0,%1,%2,%3};"
                        : "+f"(acc[fm][nf][0]), "+f"(acc[fm][nf][1]),
                          "+f"(acc[fm][nf][2]), "+f"(acc[fm][nf][3])
                        : "r"(afr[p][fm][0]), "r"(afr[p][fm][1]),
                          "r"(afr[p][fm][2]), "r"(afr[p][fm][3]),
                          "r"(bfr[p][nf * 2]), "r"(bfr[p][nf * 2 + 1]));
                }
        }
    }

    // ----- epilogue: direct NCHW fp32 stores (row r0; skip pad n>=62)
#pragma unroll
    for (int fm = 0; fm < 4; fm++) {
        int m = wm * 64 + fm * 16 + (l >> 2);
        size_t mb = (size_t)(b * COUT + m) * PIX_PER_IMG + (size_t)r0 * WOUT;
#pragma unroll
        for (int nf = 0; nf < 2; nf++) {
            int n0 = wn * 16 + nf * 8 + (l & 3) * 2;
#pragma unroll
            for (int e = 0; e < 2; e++) {
                int n = n0 + e;
                if (n < WOUT) {
                    out[mb + n]                              = acc[fm][nf][e];
                    out[mb + n + (size_t)8 * PIX_PER_IMG]    = acc[fm][nf][2 + e];
                }
            }
        }
    }
}

// ---------------------------------------------------------------------------
extern "C" void kernel_launch(void* const* d_in, const int* in_sizes, int n_in,
                              void* d_out, int out_size) {
    const float* x = (const float*)d_in[0];
    const float* W = (const float*)d_in[1];
    float* out = (float*)d_out;

    prep_all<<<XBLOCKS + WBLOCKS, 256>>>(x, W);

    cudaFuncSetAttribute(xorconv_main,
                         cudaFuncAttributeMaxDynamicSharedMemorySize, SMEM_BYTES);
    dim3 gm(HOUT, BDIM);   // 62 rows x 32 images
    xorconv_main<<<gm, 512, SMEM_BYTES>>>(out);
}